// round 1
// baseline (speedup 1.0000x reference)
#include <cuda_runtime.h>
#include <math.h>

#define BATCH   1024
#define N_IN    1024
#define NLAYERS 5
#define NPL     2048
#define FANIN   16
#define N_OUT   256
// Layer 4 only reads rows < N_IN + 4*NPL = 9216; its outputs go straight to d_out.
#define W_ROWS  (N_IN + 4 * NPL)   // 9216

// Transposed value buffer: valsT[row(c), batch(b)] — each logical column is a
// contiguous 4KB row so batch-parallel gathers are fully coalesced.
__device__ float g_vals[(size_t)W_ROWS * BATCH];

// ---------------------------------------------------------------------------
// Transpose inputs [B, N_IN] -> g_vals[N_IN, B]
// ---------------------------------------------------------------------------
__global__ void transpose_in_kernel(const float* __restrict__ in) {
    __shared__ float tile[32][33];
    int bx = blockIdx.x * 32;  // column tile (c)
    int by = blockIdx.y * 32;  // batch tile (b)
    int tx = threadIdx.x, ty = threadIdx.y;

    int x = bx + tx;
#pragma unroll
    for (int j = 0; j < 32; j += 8) {
        int y = by + ty + j;
        tile[ty + j][tx] = in[(size_t)y * N_IN + x];   // tile[r][c] = in[by+r][bx+c]
    }
    __syncthreads();

    int xo = by + tx;  // batch index
#pragma unroll
    for (int j = 0; j < 32; j += 8) {
        int yo = bx + ty + j;  // column index
        g_vals[(size_t)yo * BATCH + xo] = tile[tx][ty + j];
    }
}

// ---------------------------------------------------------------------------
// One hidden layer: block = one node, 256 threads = 1024 batch (float4 each).
// acc[b] = bias[n] + sum_f w[n,f] * valsT[src[n,f], b];  tanh;  write valsT row.
// ---------------------------------------------------------------------------
__global__ void __launch_bounds__(256) layer_kernel(
    const int*   __restrict__ src,     // [NPL, FANIN] for this layer
    const float* __restrict__ wgt,     // [NPL, FANIN]
    const float* __restrict__ bias,    // [NPL]
    int out_base_row)                  // N_IN + l*NPL
{
    const int n = blockIdx.x;
    const int t = threadIdx.x;

    const int*   s = src + n * FANIN;
    const float* w = wgt + n * FANIN;

    float bv = __ldg(bias + n);
    float4 acc = make_float4(bv, bv, bv, bv);

#pragma unroll
    for (int f = 0; f < FANIN; f++) {
        int   c  = __ldg(s + f);
        float wf = __ldg(w + f);
        float4 v = *reinterpret_cast<const float4*>(&g_vals[(size_t)c * BATCH + t * 4]);
        acc.x = fmaf(wf, v.x, acc.x);
        acc.y = fmaf(wf, v.y, acc.y);
        acc.z = fmaf(wf, v.z, acc.z);
        acc.w = fmaf(wf, v.w, acc.w);
    }

    acc.x = tanhf(acc.x);
    acc.y = tanhf(acc.y);
    acc.z = tanhf(acc.z);
    acc.w = tanhf(acc.w);

    *reinterpret_cast<float4*>(&g_vals[(size_t)(out_base_row + n) * BATCH + t * 4]) = acc;
}

// ---------------------------------------------------------------------------
// Final layer: only the last N_OUT nodes matter. sigmoid, write d_out [B, N_OUT].
// ---------------------------------------------------------------------------
__global__ void __launch_bounds__(256) final_layer_kernel(
    const int*   __restrict__ src,     // layer-4 [NPL, FANIN]
    const float* __restrict__ wgt,
    const float* __restrict__ bias,
    float*       __restrict__ out)     // [BATCH, N_OUT]
{
    const int j = blockIdx.x;            // 0..N_OUT-1
    const int n = NPL - N_OUT + j;       // node within layer 4
    const int t = threadIdx.x;

    const int*   s = src + n * FANIN;
    const float* w = wgt + n * FANIN;

    float bv = __ldg(bias + n);
    float4 acc = make_float4(bv, bv, bv, bv);

#pragma unroll
    for (int f = 0; f < FANIN; f++) {
        int   c  = __ldg(s + f);
        float wf = __ldg(w + f);
        float4 v = *reinterpret_cast<const float4*>(&g_vals[(size_t)c * BATCH + t * 4]);
        acc.x = fmaf(wf, v.x, acc.x);
        acc.y = fmaf(wf, v.y, acc.y);
        acc.z = fmaf(wf, v.z, acc.z);
        acc.w = fmaf(wf, v.w, acc.w);
    }

    // sigmoid
    acc.x = 1.0f / (1.0f + expf(-acc.x));
    acc.y = 1.0f / (1.0f + expf(-acc.y));
    acc.z = 1.0f / (1.0f + expf(-acc.z));
    acc.w = 1.0f / (1.0f + expf(-acc.w));

    const int b = t * 4;
    out[(size_t)(b + 0) * N_OUT + j] = acc.x;
    out[(size_t)(b + 1) * N_OUT + j] = acc.y;
    out[(size_t)(b + 2) * N_OUT + j] = acc.z;
    out[(size_t)(b + 3) * N_OUT + j] = acc.w;
}

// ---------------------------------------------------------------------------
extern "C" void kernel_launch(void* const* d_in, const int* in_sizes, int n_in,
                              void* d_out, int out_size) {
    const float* inputs   = (const float*)d_in[0];   // [B, N_IN]
    const int*   edge_src = (const int*)  d_in[1];   // [L, NPL, FANIN]
    const float* edge_w   = (const float*)d_in[2];   // [L, NPL, FANIN]
    const float* biases   = (const float*)d_in[3];   // [L, NPL]
    float*       out      = (float*)d_out;

    transpose_in_kernel<<<dim3(N_IN / 32, BATCH / 32), dim3(32, 8)>>>(inputs);

    for (int l = 0; l < NLAYERS - 1; l++) {
        layer_kernel<<<NPL, 256>>>(
            edge_src + (size_t)l * NPL * FANIN,
            edge_w   + (size_t)l * NPL * FANIN,
            biases   + (size_t)l * NPL,
            N_IN + l * NPL);
    }

    const int lf = NLAYERS - 1;
    final_layer_kernel<<<N_OUT, 256>>>(
        edge_src + (size_t)lf * NPL * FANIN,
        edge_w   + (size_t)lf * NPL * FANIN,
        biases   + (size_t)lf * NPL,
        out);
}

// round 3
// speedup vs baseline: 1.0942x; 1.0942x over previous
#include <cuda_runtime.h>
#include <cuda_fp16.h>
#include <math.h>

#define BATCH   1024
#define N_IN    1024
#define NLAYERS 5
#define NPL     2048
#define FANIN   16
#define N_OUT   256
// Layer 4 only reads rows < N_IN + 4*NPL = 9216; its outputs go straight to d_out.
#define W_ROWS  (N_IN + 4 * NPL)   // 9216

// Transposed value buffer in fp16: valsT[row(c), batch(b)].
// Each logical column is a contiguous 2KB row -> coalesced batch-parallel gathers.
// 9216 * 1024 * 2B = 18.9 MB (fully L2-resident).
__device__ __half g_vals[(size_t)W_ROWS * BATCH];

// ---------------------------------------------------------------------------
// Transpose + convert inputs [B, N_IN] f32 -> g_vals[N_IN, B] f16
// ---------------------------------------------------------------------------
__global__ void transpose_in_kernel(const float* __restrict__ in) {
    __shared__ float tile[32][33];
    int bx = blockIdx.x * 32;  // column tile (c)
    int by = blockIdx.y * 32;  // batch tile (b)
    int tx = threadIdx.x, ty = threadIdx.y;

    int x = bx + tx;
#pragma unroll
    for (int j = 0; j < 32; j += 8) {
        int y = by + ty + j;
        tile[ty + j][tx] = in[(size_t)y * N_IN + x];   // tile[r][c] = in[by+r][bx+c]
    }
    __syncthreads();

    int xo = by + tx;  // batch index
#pragma unroll
    for (int j = 0; j < 32; j += 8) {
        int yo = bx + ty + j;  // column index
        g_vals[(size_t)yo * BATCH + xo] = __float2half_rn(tile[tx][ty + j]);
    }
}

// ---------------------------------------------------------------------------
// One hidden layer: block = one node, 256 threads = 1024 batch (4 halves each).
// fp32 accumulate, tanh, store fp16 row.
// ---------------------------------------------------------------------------
__global__ void __launch_bounds__(256) layer_kernel(
    const int*   __restrict__ src,     // [NPL, FANIN] for this layer
    const float* __restrict__ wgt,     // [NPL, FANIN]
    const float* __restrict__ bias,    // [NPL]
    int out_base_row)                  // N_IN + l*NPL
{
    const int n = blockIdx.x;
    const int t = threadIdx.x;

    // Vector-load all 16 indices and weights up front.
    int   sidx[FANIN];
    float wv[FANIN];
    {
        const int4*   s4 = (const int4*)(src + n * FANIN);
        const float4* w4 = (const float4*)(wgt + n * FANIN);
#pragma unroll
        for (int q = 0; q < FANIN / 4; q++) {
            int4   si = __ldg(s4 + q);
            float4 wi = __ldg(w4 + q);
            sidx[q * 4 + 0] = si.x; sidx[q * 4 + 1] = si.y;
            sidx[q * 4 + 2] = si.z; sidx[q * 4 + 3] = si.w;
            wv[q * 4 + 0] = wi.x; wv[q * 4 + 1] = wi.y;
            wv[q * 4 + 2] = wi.z; wv[q * 4 + 3] = wi.w;
        }
    }

    float bv = __ldg(bias + n);
    float4 acc = make_float4(bv, bv, bv, bv);

#pragma unroll
    for (int f = 0; f < FANIN; f++) {
        const __half2* row = (const __half2*)&g_vals[(size_t)sidx[f] * BATCH + t * 4];
        __half2 h01 = row[0];
        __half2 h23 = row[1];
        float2 f01 = __half22float2(h01);
        float2 f23 = __half22float2(h23);
        float wf = wv[f];
        acc.x = fmaf(wf, f01.x, acc.x);
        acc.y = fmaf(wf, f01.y, acc.y);
        acc.z = fmaf(wf, f23.x, acc.z);
        acc.w = fmaf(wf, f23.y, acc.w);
    }

    acc.x = tanhf(acc.x);
    acc.y = tanhf(acc.y);
    acc.z = tanhf(acc.z);
    acc.w = tanhf(acc.w);

    __half2* out = (__half2*)&g_vals[(size_t)(out_base_row + n) * BATCH + t * 4];
    out[0] = __floats2half2_rn(acc.x, acc.y);
    out[1] = __floats2half2_rn(acc.z, acc.w);
}

// ---------------------------------------------------------------------------
// Final layer: only the last N_OUT nodes matter. sigmoid, write d_out [B, N_OUT] f32.
// ---------------------------------------------------------------------------
__global__ void __launch_bounds__(256) final_layer_kernel(
    const int*   __restrict__ src,     // layer-4 [NPL, FANIN]
    const float* __restrict__ wgt,
    const float* __restrict__ bias,
    float*       __restrict__ out)     // [BATCH, N_OUT]
{
    const int j = blockIdx.x;            // 0..N_OUT-1
    const int n = NPL - N_OUT + j;       // node within layer 4
    const int t = threadIdx.x;

    int   sidx[FANIN];
    float wv[FANIN];
    {
        const int4*   s4 = (const int4*)(src + n * FANIN);
        const float4* w4 = (const float4*)(wgt + n * FANIN);
#pragma unroll
        for (int q = 0; q < FANIN / 4; q++) {
            int4   si = __ldg(s4 + q);
            float4 wi = __ldg(w4 + q);
            sidx[q * 4 + 0] = si.x; sidx[q * 4 + 1] = si.y;
            sidx[q * 4 + 2] = si.z; sidx[q * 4 + 3] = si.w;
            wv[q * 4 + 0] = wi.x; wv[q * 4 + 1] = wi.y;
            wv[q * 4 + 2] = wi.z; wv[q * 4 + 3] = wi.w;
        }
    }

    float bv = __ldg(bias + n);
    float4 acc = make_float4(bv, bv, bv, bv);

#pragma unroll
    for (int f = 0; f < FANIN; f++) {
        const __half2* row = (const __half2*)&g_vals[(size_t)sidx[f] * BATCH + t * 4];
        __half2 h01 = row[0];
        __half2 h23 = row[1];
        float2 f01 = __half22float2(h01);
        float2 f23 = __half22float2(h23);
        float wf = wv[f];
        acc.x = fmaf(wf, f01.x, acc.x);
        acc.y = fmaf(wf, f01.y, acc.y);
        acc.z = fmaf(wf, f23.x, acc.z);
        acc.w = fmaf(wf, f23.y, acc.w);
    }

    acc.x = 1.0f / (1.0f + expf(-acc.x));
    acc.y = 1.0f / (1.0f + expf(-acc.y));
    acc.z = 1.0f / (1.0f + expf(-acc.z));
    acc.w = 1.0f / (1.0f + expf(-acc.w));

    const int b = t * 4;
    out[(size_t)(b + 0) * N_OUT + j] = acc.x;
    out[(size_t)(b + 1) * N_OUT + j] = acc.y;
    out[(size_t)(b + 2) * N_OUT + j] = acc.z;
    out[(size_t)(b + 3) * N_OUT + j] = acc.w;
}

// ---------------------------------------------------------------------------
extern "C" void kernel_launch(void* const* d_in, const int* in_sizes, int n_in,
                              void* d_out, int out_size) {
    const float* inputs   = (const float*)d_in[0];   // [B, N_IN]
    const int*   edge_src = (const int*)  d_in[1];   // [L, NPL, FANIN]
    const float* edge_w   = (const float*)d_in[2];   // [L, NPL, FANIN]
    const float* biases   = (const float*)d_in[3];   // [L, NPL]
    float*       out      = (float*)d_out;

    transpose_in_kernel<<<dim3(N_IN / 32, BATCH / 32), dim3(32, 8)>>>(inputs);

    for (int l = 0; l < NLAYERS - 1; l++) {
        layer_kernel<<<NPL, 256>>>(
            edge_src + (size_t)l * NPL * FANIN,
            edge_w   + (size_t)l * NPL * FANIN,
            biases   + (size_t)l * NPL,
            N_IN + l * NPL);
    }

    const int lf = NLAYERS - 1;
    final_layer_kernel<<<N_OUT, 256>>>(
        edge_src + (size_t)lf * NPL * FANIN,
        edge_w   + (size_t)lf * NPL * FANIN,
        biases   + (size_t)lf * NPL,
        out);
}

// round 4
// speedup vs baseline: 1.2199x; 1.1148x over previous
#include <cuda_runtime.h>
#include <cuda_fp16.h>
#include <math.h>

#define BATCH   1024
#define N_IN    1024
#define NLAYERS 5
#define NPL     2048
#define FANIN   16
#define N_OUT   256
// Layer 4 only reads rows < N_IN + 4*NPL = 9216; its outputs go straight to d_out.
#define W_ROWS  (N_IN + 4 * NPL)   // 9216

// Transposed value buffer in fp16: valsT[row(c), batch(b)].
// 9216 * 1024 * 2B = 18.9 MB (fully L2-resident).
__device__ __half g_vals[(size_t)W_ROWS * BATCH];

__device__ __forceinline__ float tanh_approx(float x) {
    float y;
    asm("tanh.approx.f32 %0, %1;" : "=f"(y) : "f"(x));
    return y;
}

// ---------------------------------------------------------------------------
// Transpose + convert inputs [B, N_IN] f32 -> g_vals[N_IN, B] f16
// ---------------------------------------------------------------------------
__global__ void transpose_in_kernel(const float* __restrict__ in) {
    __shared__ float tile[32][33];
    int bx = blockIdx.x * 32;  // column tile (c)
    int by = blockIdx.y * 32;  // batch tile (b)
    int tx = threadIdx.x, ty = threadIdx.y;

    int x = bx + tx;
#pragma unroll
    for (int j = 0; j < 32; j += 8) {
        int y = by + ty + j;
        tile[ty + j][tx] = in[(size_t)y * N_IN + x];
    }
    __syncthreads();

    int xo = by + tx;  // batch index
#pragma unroll
    for (int j = 0; j < 32; j += 8) {
        int yo = bx + ty + j;  // column index
        g_vals[(size_t)yo * BATCH + xo] = __float2half_rn(tile[tx][ty + j]);
    }
}

// ---------------------------------------------------------------------------
// One hidden layer. Block = 2 nodes x 128 threads; each thread owns 8 batch
// elements (one 16B LDG.128 per fanin). fp32 accumulate, HW tanh, fp16 store.
// ---------------------------------------------------------------------------
__global__ void __launch_bounds__(256) layer_kernel(
    const int*   __restrict__ src,     // [NPL, FANIN]
    const float* __restrict__ wgt,     // [NPL, FANIN]
    const float* __restrict__ bias,    // [NPL]
    int out_base_row)                  // N_IN + l*NPL
{
    const int n = blockIdx.x * 2 + (threadIdx.x >> 7);
    const int t = threadIdx.x & 127;       // 0..127, owns batch [t*8, t*8+8)

    int   sidx[FANIN];
    float wv[FANIN];
    {
        const int4*   s4 = (const int4*)(src + n * FANIN);
        const float4* w4 = (const float4*)(wgt + n * FANIN);
#pragma unroll
        for (int q = 0; q < FANIN / 4; q++) {
            int4   si = __ldg(s4 + q);
            float4 wi = __ldg(w4 + q);
            sidx[q * 4 + 0] = si.x; sidx[q * 4 + 1] = si.y;
            sidx[q * 4 + 2] = si.z; sidx[q * 4 + 3] = si.w;
            wv[q * 4 + 0] = wi.x; wv[q * 4 + 1] = wi.y;
            wv[q * 4 + 2] = wi.z; wv[q * 4 + 3] = wi.w;
        }
    }

    float bv = __ldg(bias + n);
    float acc[8];
#pragma unroll
    for (int i = 0; i < 8; i++) acc[i] = bv;

#pragma unroll
    for (int f = 0; f < FANIN; f++) {
        uint4 v = *(const uint4*)&g_vals[(size_t)sidx[f] * BATCH + t * 8];
        float wf = wv[f];
        __half2 h0 = *(__half2*)&v.x;
        __half2 h1 = *(__half2*)&v.y;
        __half2 h2 = *(__half2*)&v.z;
        __half2 h3 = *(__half2*)&v.w;
        float2 f0 = __half22float2(h0);
        float2 f1 = __half22float2(h1);
        float2 f2 = __half22float2(h2);
        float2 f3 = __half22float2(h3);
        acc[0] = fmaf(wf, f0.x, acc[0]);
        acc[1] = fmaf(wf, f0.y, acc[1]);
        acc[2] = fmaf(wf, f1.x, acc[2]);
        acc[3] = fmaf(wf, f1.y, acc[3]);
        acc[4] = fmaf(wf, f2.x, acc[4]);
        acc[5] = fmaf(wf, f2.y, acc[5]);
        acc[6] = fmaf(wf, f3.x, acc[6]);
        acc[7] = fmaf(wf, f3.y, acc[7]);
    }

#pragma unroll
    for (int i = 0; i < 8; i++) acc[i] = tanh_approx(acc[i]);

    uint4 o;
    *(__half2*)&o.x = __floats2half2_rn(acc[0], acc[1]);
    *(__half2*)&o.y = __floats2half2_rn(acc[2], acc[3]);
    *(__half2*)&o.z = __floats2half2_rn(acc[4], acc[5]);
    *(__half2*)&o.w = __floats2half2_rn(acc[6], acc[7]);
    *(uint4*)&g_vals[(size_t)(out_base_row + n) * BATCH + t * 8] = o;
}

// ---------------------------------------------------------------------------
// Final layer: only the last N_OUT nodes matter. Accurate sigmoid, f32 out.
// Block = 2 nodes x 128 threads, 8 batch elems/thread.
// ---------------------------------------------------------------------------
__global__ void __launch_bounds__(256) final_layer_kernel(
    const int*   __restrict__ src,     // layer-4 [NPL, FANIN]
    const float* __restrict__ wgt,
    const float* __restrict__ bias,
    float*       __restrict__ out)     // [BATCH, N_OUT]
{
    const int j = blockIdx.x * 2 + (threadIdx.x >> 7);  // 0..N_OUT-1
    const int n = NPL - N_OUT + j;
    const int t = threadIdx.x & 127;

    int   sidx[FANIN];
    float wv[FANIN];
    {
        const int4*   s4 = (const int4*)(src + n * FANIN);
        const float4* w4 = (const float4*)(wgt + n * FANIN);
#pragma unroll
        for (int q = 0; q < FANIN / 4; q++) {
            int4   si = __ldg(s4 + q);
            float4 wi = __ldg(w4 + q);
            sidx[q * 4 + 0] = si.x; sidx[q * 4 + 1] = si.y;
            sidx[q * 4 + 2] = si.z; sidx[q * 4 + 3] = si.w;
            wv[q * 4 + 0] = wi.x; wv[q * 4 + 1] = wi.y;
            wv[q * 4 + 2] = wi.z; wv[q * 4 + 3] = wi.w;
        }
    }

    float bv = __ldg(bias + n);
    float acc[8];
#pragma unroll
    for (int i = 0; i < 8; i++) acc[i] = bv;

#pragma unroll
    for (int f = 0; f < FANIN; f++) {
        uint4 v = *(const uint4*)&g_vals[(size_t)sidx[f] * BATCH + t * 8];
        float wf = wv[f];
        __half2 h0 = *(__half2*)&v.x;
        __half2 h1 = *(__half2*)&v.y;
        __half2 h2 = *(__half2*)&v.z;
        __half2 h3 = *(__half2*)&v.w;
        float2 f0 = __half22float2(h0);
        float2 f1 = __half22float2(h1);
        float2 f2 = __half22float2(h2);
        float2 f3 = __half22float2(h3);
        acc[0] = fmaf(wf, f0.x, acc[0]);
        acc[1] = fmaf(wf, f0.y, acc[1]);
        acc[2] = fmaf(wf, f1.x, acc[2]);
        acc[3] = fmaf(wf, f1.y, acc[3]);
        acc[4] = fmaf(wf, f2.x, acc[4]);
        acc[5] = fmaf(wf, f2.y, acc[5]);
        acc[6] = fmaf(wf, f3.x, acc[6]);
        acc[7] = fmaf(wf, f3.y, acc[7]);
    }

    const int b = t * 8;
#pragma unroll
    for (int i = 0; i < 8; i++) {
        float s = 1.0f / (1.0f + expf(-acc[i]));
        out[(size_t)(b + i) * N_OUT + j] = s;
    }
}

// ---------------------------------------------------------------------------
extern "C" void kernel_launch(void* const* d_in, const int* in_sizes, int n_in,
                              void* d_out, int out_size) {
    const float* inputs   = (const float*)d_in[0];   // [B, N_IN]
    const int*   edge_src = (const int*)  d_in[1];   // [L, NPL, FANIN]
    const float* edge_w   = (const float*)d_in[2];   // [L, NPL, FANIN]
    const float* biases   = (const float*)d_in[3];   // [L, NPL]
    float*       out      = (float*)d_out;

    transpose_in_kernel<<<dim3(N_IN / 32, BATCH / 32), dim3(32, 8)>>>(inputs);

    for (int l = 0; l < NLAYERS - 1; l++) {
        layer_kernel<<<NPL / 2, 256>>>(
            edge_src + (size_t)l * NPL * FANIN,
            edge_w   + (size_t)l * NPL * FANIN,
            biases   + (size_t)l * NPL,
            N_IN + l * NPL);
    }

    const int lf = NLAYERS - 1;
    final_layer_kernel<<<N_OUT / 2, 256>>>(
        edge_src + (size_t)lf * NPL * FANIN,
        edge_w   + (size_t)lf * NPL * FANIN,
        biases   + (size_t)lf * NPL,
        out);
}